// round 8
// baseline (speedup 1.0000x reference)
#include <cuda_runtime.h>
#include <cuda_fp16.h>
#include <stdint.h>

#define B_DIM   8192
#define F0_DIM  2048
#define F1_DIM  2304
#define F2_DIM  2560
#define O_DIM   1024
#define NNZ_DIM 262144
#define NB_DIM  1024

// ---------------- scratch (device globals; no allocation allowed) -------------
__device__ float g_W[O_DIM * F2_DIM];
__device__ float g_bias[O_DIM];
__device__ __half g_A[(size_t)B_DIM * F2_DIM];    // 42 MB, fp16 h
__device__ __half g_Wc[(size_t)O_DIM * F2_DIM];   // 5.2 MB, fp16 W

// ---------------- helpers -----------------------------------------------------
__device__ __forceinline__ uint32_t smem_u32(const void* p) {
    uint32_t a;
    asm("{ .reg .u64 t; cvta.to.shared.u64 t, %1; cvt.u32.u64 %0, t; }"
        : "=r"(a) : "l"(p));
    return a;
}

#define SW128(off) ((uint32_t)(off) ^ ((((uint32_t)(off)) >> 3) & 0x70u))

__device__ __forceinline__ void cp_async16(uint32_t saddr, const void* gptr) {
    asm volatile("cp.async.cg.shared.global [%0], [%1], 16;\n"
                 :: "r"(saddr), "l"(gptr));
}

__device__ __forceinline__ void ldsm_x4(uint32_t* r, uint32_t addr) {
    asm volatile("ldmatrix.sync.aligned.m8n8.x4.shared.b16 {%0,%1,%2,%3}, [%4];"
                 : "=r"(r[0]), "=r"(r[1]), "=r"(r[2]), "=r"(r[3]) : "r"(addr));
}

__device__ __forceinline__ void mma_f16(float* d, const uint32_t* a, const uint32_t* b) {
    asm volatile(
        "mma.sync.aligned.m16n8k16.row.col.f32.f16.f16.f32 "
        "{%0,%1,%2,%3}, {%4,%5,%6,%7}, {%8,%9}, {%0,%1,%2,%3};\n"
        : "+f"(d[0]), "+f"(d[1]), "+f"(d[2]), "+f"(d[3])
        : "r"(a[0]), "r"(a[1]), "r"(a[2]), "r"(a[3]), "r"(b[0]), "r"(b[1]));
}

// ---------------- prologue kernels -------------------------------------------
__global__ void zero_kernel() {
    int i = blockIdx.x * blockDim.x + threadIdx.x;
    if (i < O_DIM * F2_DIM / 4)
        *(float4*)(g_W + i * 4) = make_float4(0.f, 0.f, 0.f, 0.f);
    if (i < O_DIM) g_bias[i] = 0.0f;
}

__global__ void scatter_kernel(const float* __restrict__ w_vals,
                               const int*   __restrict__ w_rows,
                               const int*   __restrict__ w_cols,
                               const float* __restrict__ b_vals,
                               const int*   __restrict__ b_idx) {
    int i = blockIdx.x * blockDim.x + threadIdx.x;
    if (i < NNZ_DIM)
        atomicAdd(&g_W[w_rows[i] * F2_DIM + w_cols[i]], w_vals[i]);
    if (i < NB_DIM)
        atomicAdd(&g_bias[b_idx[i]], b_vals[i]);
}

__global__ void convw_kernel() {
    int i = blockIdx.x * blockDim.x + threadIdx.x;
    if (i >= O_DIM * F2_DIM / 4) return;
    float4 v = *(const float4*)(g_W + i * 4);
    __half2 p0 = __floats2half2_rn(v.x, v.y);
    __half2 p1 = __floats2half2_rn(v.z, v.w);
    *(__half2*)(g_Wc + i * 4)     = p0;
    *(__half2*)(g_Wc + i * 4 + 2) = p1;
}

// one block per batch row; all gathers hit smem, GMEM fully coalesced
__global__ void __launch_bounds__(256)
build_a_kernel(const float* __restrict__ x,
               const float* __restrict__ e1w,
               const float* __restrict__ e2w,
               const int*   __restrict__ e1p,
               const int*   __restrict__ e2p) {
    __shared__ float sh[F2_DIM];
    const int tid = threadIdx.x;
    const int b = blockIdx.x;

    const float4* xr = (const float4*)(x + (size_t)b * F0_DIM);
#pragma unroll
    for (int t = 0; t < F0_DIM / 4 / 256; t++)          // 2 iters
        ((float4*)sh)[tid + t * 256] = xr[tid + t * 256];
    __syncthreads();

    {   // E1 == 256 == blockDim
        int c = tid;
        float t = sh[__ldg(&e1p[c])] * __ldg(&e1w[c]);
        sh[F0_DIM + c] = fmaxf(t, 0.0f);
    }
    __syncthreads();
    {   // E2 == 256
        int c = tid;
        float t = sh[__ldg(&e2p[c])] * __ldg(&e2w[c]);
        sh[F1_DIM + c] = fmaxf(t, 0.0f);
    }
    __syncthreads();

    __half* base = g_A + (size_t)b * F2_DIM;
#pragma unroll
    for (int t = 0; t < F2_DIM / 4 / 256 + 1; t++) {    // 3 iters (last partial)
        int i = tid + t * 256;
        if (i < F2_DIM / 4) {
            float4 v = *(const float4*)(sh + i * 4);
            __half2 p0 = __floats2half2_rn(v.x, v.y);
            __half2 p1 = __floats2half2_rn(v.z, v.w);
            *(__half2*)(base + i * 4)     = p0;
            *(__half2*)(base + i * 4 + 2) = p1;
        }
    }
}

// ---------------- fp16 HMMA GEMM: out = A @ Wc^T + bias -----------------------
#define BM 128
#define BN 256
#define BK 128
#define NTHREADS 256
#define STAGES 2
#define A_STAGE (BM * BK * 2)               /* 32768 B */
#define B_STAGE (BN * BK * 2)               /* 65536 B */
#define STAGE_BYTES (A_STAGE + B_STAGE)     /* 98304 B */
#define KT (F2_DIM / BK)                    /* 20 */
#define DYN_SMEM (STAGES * STAGE_BYTES)     /* 196608 B */

__global__ void __launch_bounds__(NTHREADS, 1)
gemm_kernel(float* __restrict__ out) {
    extern __shared__ char dynsm[];
    const int tid  = threadIdx.x;
    const int wid  = tid >> 5;
    const int lane = tid & 31;
    const int wm   = wid >> 2;       // 0..1, 64 rows each
    const int wn   = wid & 3;        // 0..3, 64 cols each
    const int m0 = blockIdx.x * BM;
    const int n0 = blockIdx.y * BN;
    const uint32_t smbase = smem_u32(dynsm);

    float acc[4][8][4];
#pragma unroll
    for (int mt = 0; mt < 4; mt++)
#pragma unroll
        for (int nt = 0; nt < 8; nt++)
#pragma unroll
            for (int r = 0; r < 4; r++) acc[mt][nt][r] = 0.0f;

    // ldmatrix lane address components (logical, pre-swizzle, byte units)
    // rows are 256B wide now (BK=128 fp16)
    const uint32_t a_row = (uint32_t)(wm * 64 + (lane & 15));
    const uint32_t a_col = (uint32_t)((lane >> 4) * 16);
    const uint32_t b_row = (uint32_t)(wn * 64 + (lane & 7) + ((lane >> 4) << 3));
    const uint32_t b_col = (uint32_t)(((lane >> 3) & 1) * 16);

    auto load_tile = [&](int s, int kt) {
        int k0 = kt * BK;
        uint32_t As = smbase + s * STAGE_BYTES;
        uint32_t Bs = As + A_STAGE;
        const char* gA = (const char*)g_A  + (size_t)k0 * 2;
        const char* gB = (const char*)g_Wc + (size_t)k0 * 2;
#pragma unroll
        for (int t = 0; t < 8; t++) {                    // A: 2048 16B ops
            int o = tid + t * NTHREADS;
            int r = o >> 4;
            int c = (o & 15) * 16;
            cp_async16(As + SW128(r * 256 + c),
                       gA + (size_t)(m0 + r) * (F2_DIM * 2) + c);
        }
#pragma unroll
        for (int t = 0; t < 16; t++) {                   // B: 4096 16B ops
            int o = tid + t * NTHREADS;
            int r = o >> 4;
            int c = (o & 15) * 16;
            cp_async16(Bs + SW128(r * 256 + c),
                       gB + (size_t)(n0 + r) * (F2_DIM * 2) + c);
        }
    };

    load_tile(0, 0);
    asm volatile("cp.async.commit_group;\n");

    for (int kt = 0; kt < KT; kt++) {
        asm volatile("cp.async.wait_group 0;\n");
        __syncthreads();

        int kn = kt + 1;
        if (kn < KT) load_tile(kn & 1, kn);
        asm volatile("cp.async.commit_group;\n");

        const uint32_t As = smbase + (kt & 1) * STAGE_BYTES;
        const uint32_t Bs = As + A_STAGE;

        // register double-buffered fragments over 8 k16 steps
        uint32_t a[2][4][4], b[2][4][4];
        auto load_frags = [&](int pb, int ks) {
#pragma unroll
            for (int mt = 0; mt < 4; mt++)
                ldsm_x4(a[pb][mt], As + SW128((a_row + mt * 16) * 256 + ks * 32 + a_col));
#pragma unroll
            for (int n2 = 0; n2 < 4; n2++)
                ldsm_x4(b[pb][n2], Bs + SW128((b_row + n2 * 16) * 256 + ks * 32 + b_col));
        };

        load_frags(0, 0);
#pragma unroll
        for (int ks = 0; ks < 8; ks++) {                 // BK=128 -> 8 k16 steps
            int cur = ks & 1;
            if (ks < 7) load_frags(cur ^ 1, ks + 1);
#pragma unroll
            for (int mt = 0; mt < 4; mt++)
#pragma unroll
                for (int nt = 0; nt < 8; nt++)
                    mma_f16(acc[mt][nt], a[cur][mt], &b[cur][nt >> 1][(nt & 1) * 2]);
        }
    }

    // epilogue: + bias, float2 stores
    const int r0 = m0 + wm * 64 + (lane >> 2);
    const int c0 = n0 + wn * 64 + (lane & 3) * 2;
#pragma unroll
    for (int mt = 0; mt < 4; mt++) {
        int row = r0 + mt * 16;
#pragma unroll
        for (int nt = 0; nt < 8; nt++) {
            int col = c0 + nt * 8;
            float2 bv = *(const float2*)(g_bias + col);
            float2 v0 = make_float2(acc[mt][nt][0] + bv.x, acc[mt][nt][1] + bv.y);
            float2 v1 = make_float2(acc[mt][nt][2] + bv.x, acc[mt][nt][3] + bv.y);
            *(float2*)(out + (size_t)row * O_DIM + col)       = v0;
            *(float2*)(out + (size_t)(row + 8) * O_DIM + col) = v1;
        }
    }
}

// ---------------- launch ------------------------------------------------------
extern "C" void kernel_launch(void* const* d_in, const int* in_sizes, int n_in,
                              void* d_out, int out_size) {
    const float* x     = (const float*)d_in[0];
    const float* e1w   = (const float*)d_in[1];
    const float* e2w   = (const float*)d_in[2];
    const float* wvals = (const float*)d_in[3];
    const float* bvals = (const float*)d_in[4];
    const int*   e1p   = (const int*)d_in[5];
    const int*   e2p   = (const int*)d_in[6];
    const int*   wrows = (const int*)d_in[7];
    const int*   wcols = (const int*)d_in[8];
    const int*   bidx  = (const int*)d_in[9];
    float* out = (float*)d_out;

    cudaFuncSetAttribute(gemm_kernel, cudaFuncAttributeMaxDynamicSharedMemorySize,
                         DYN_SMEM);

    zero_kernel<<<(O_DIM * F2_DIM / 4 + 255) / 256, 256>>>();
    scatter_kernel<<<(NNZ_DIM + 255) / 256, 256>>>(wvals, wrows, wcols, bvals, bidx);
    convw_kernel<<<(O_DIM * F2_DIM / 4 + 255) / 256, 256>>>();
    build_a_kernel<<<B_DIM, 256>>>(x, e1w, e2w, e1p, e2p);

    dim3 grid(B_DIM / BM, O_DIM / BN);
    gemm_kernel<<<grid, NTHREADS, DYN_SMEM>>>(out);
}

// round 11
// speedup vs baseline: 1.0560x; 1.0560x over previous
#include <cuda_runtime.h>
#include <cuda_fp16.h>
#include <stdint.h>

#define B_DIM   8192
#define F0_DIM  2048
#define F1_DIM  2304
#define F2_DIM  2560
#define O_DIM   1024
#define NNZ_DIM 262144
#define NB_DIM  1024

// ---------------- scratch (device globals; zero-initialized at load) ----------
__device__ float g_W[O_DIM * F2_DIM];
__device__ float g_bias[O_DIM];
__device__ float g_biasf[O_DIM];
__device__ __half g_A[(size_t)B_DIM * F2_DIM];    // 42 MB, fp16 h
__device__ __half g_Wc[(size_t)O_DIM * F2_DIM];   // 5.2 MB, fp16 W

// ---------------- helpers -----------------------------------------------------
__device__ __forceinline__ uint32_t smem_u32(const void* p) {
    uint32_t a;
    asm("{ .reg .u64 t; cvta.to.shared.u64 t, %1; cvt.u32.u64 %0, t; }"
        : "=r"(a) : "l"(p));
    return a;
}

#define SW128(off) ((uint32_t)(off) ^ ((((uint32_t)(off)) >> 3) & 0x70u))

__device__ __forceinline__ void cp_async16(uint32_t saddr, const void* gptr) {
    asm volatile("cp.async.cg.shared.global [%0], [%1], 16;\n"
                 :: "r"(saddr), "l"(gptr));
}

__device__ __forceinline__ void ldsm_x4(uint32_t* r, uint32_t addr) {
    asm volatile("ldmatrix.sync.aligned.m8n8.x4.shared.b16 {%0,%1,%2,%3}, [%4];"
                 : "=r"(r[0]), "=r"(r[1]), "=r"(r[2]), "=r"(r[3]) : "r"(addr));
}

__device__ __forceinline__ void mma_f16(float* d, const uint32_t* a, const uint32_t* b) {
    asm volatile(
        "mma.sync.aligned.m16n8k16.row.col.f32.f16.f16.f32 "
        "{%0,%1,%2,%3}, {%4,%5,%6,%7}, {%8,%9}, {%0,%1,%2,%3};\n"
        : "+f"(d[0]), "+f"(d[1]), "+f"(d[2]), "+f"(d[3])
        : "r"(a[0]), "r"(a[1]), "r"(a[2]), "r"(a[3]), "r"(b[0]), "r"(b[1]));
}

// ---------------- fused prologue: build A (4 rows/block) + scatter ------------
#define BA_BLOCKS (B_DIM / 4)     /* 2048 */
#define SC_BLOCKS (NNZ_DIM / 256) /* 1024 */

__global__ void __launch_bounds__(256)
fused_pre_kernel(const float* __restrict__ x,
                 const float* __restrict__ e1w,
                 const float* __restrict__ e2w,
                 const int*   __restrict__ e1p,
                 const int*   __restrict__ e2p,
                 const float* __restrict__ w_vals,
                 const int*   __restrict__ w_rows,
                 const int*   __restrict__ w_cols,
                 const float* __restrict__ b_vals,
                 const int*   __restrict__ b_idx) {
    const int tid = threadIdx.x;

    if (blockIdx.x >= BA_BLOCKS) {
        // ---- COO weight + bias scatter (atomics into zeroed g_W / g_bias) ----
        int i = (blockIdx.x - BA_BLOCKS) * 256 + tid;
        atomicAdd(&g_W[w_rows[i] * F2_DIM + w_cols[i]], w_vals[i]);
        if (i < NB_DIM)
            atomicAdd(&g_bias[b_idx[i]], b_vals[i]);
        return;
    }

    // ---- build A: 4 batch rows per block, gathers via smem -------------------
    __shared__ float sh[4 * F2_DIM];          // 40 KB
    const int b0 = blockIdx.x * 4;

    // load x rows (4 x 512 float4), coalesced
#pragma unroll
    for (int t = 0; t < 8; t++) {
        int idx = tid + t * 256;              // 0..2047
        int r = idx >> 9;
        int c = idx & 511;
        ((float4*)(sh + r * F2_DIM))[c] =
            ((const float4*)(x + (size_t)(b0 + r) * F0_DIM))[c];
    }
    __syncthreads();

    {   // E1 == 256 == blockDim; 4 rows per thread (ILP)
        int c = tid;
        int p = __ldg(&e1p[c]);
        float w = __ldg(&e1w[c]);
#pragma unroll
        for (int r = 0; r < 4; r++)
            sh[r * F2_DIM + F0_DIM + c] = fmaxf(sh[r * F2_DIM + p] * w, 0.0f);
    }
    __syncthreads();
    {   // E2 == 256
        int c = tid;
        int p = __ldg(&e2p[c]);
        float w = __ldg(&e2w[c]);
#pragma unroll
        for (int r = 0; r < 4; r++)
            sh[r * F2_DIM + F1_DIM + c] = fmaxf(sh[r * F2_DIM + p] * w, 0.0f);
    }
    __syncthreads();

#pragma unroll
    for (int r = 0; r < 4; r++) {
        __half* base = g_A + (size_t)(b0 + r) * F2_DIM;
        const float* row = sh + r * F2_DIM;
#pragma unroll
        for (int t = 0; t < 3; t++) {         // 640 float4 groups / 256
            int i = tid + t * 256;
            if (i < F2_DIM / 4) {
                float4 v = *(const float4*)(row + i * 4);
                __half2 p0 = __floats2half2_rn(v.x, v.y);
                __half2 p1 = __floats2half2_rn(v.z, v.w);
                *(__half2*)(base + i * 4)     = p0;
                *(__half2*)(base + i * 4 + 2) = p1;
            }
        }
    }
}

// ---------------- convw: W fp32 -> fp16, and re-zero W/bias for next replay ---
__global__ void convw_kernel() {
    int i = blockIdx.x * blockDim.x + threadIdx.x;
    if (i >= O_DIM * F2_DIM / 4) return;
    float4 v = *(const float4*)(g_W + i * 4);
    __half2 p0 = __floats2half2_rn(v.x, v.y);
    __half2 p1 = __floats2half2_rn(v.z, v.w);
    *(__half2*)(g_Wc + i * 4)     = p0;
    *(__half2*)(g_Wc + i * 4 + 2) = p1;
    *(float4*)(g_W + i * 4) = make_float4(0.f, 0.f, 0.f, 0.f);   // pre-zero for next call
    if (i < O_DIM / 4) {                                         // bias: copy then zero
        float4 b = *(const float4*)(g_bias + i * 4);
        *(float4*)(g_biasf + i * 4) = b;
        *(float4*)(g_bias + i * 4)  = make_float4(0.f, 0.f, 0.f, 0.f);
    }
}

// ---------------- fp16 HMMA GEMM: out = A @ Wc^T + bias (R6 config) -----------
#define BM 128
#define BN 256
#define BK 64
#define STAGES 4
#define A_STAGE (BM * BK * 2)               /* 16384 B */
#define B_STAGE (BN * BK * 2)               /* 32768 B */
#define STAGE_BYTES (A_STAGE + B_STAGE)     /* 49152 B */
#define KT (F2_DIM / BK)                    /* 40 */
#define DYN_SMEM (STAGES * STAGE_BYTES)     /* 196608 B */

__global__ void __launch_bounds__(256, 1)
gemm_kernel(float* __restrict__ out) {
    extern __shared__ char dynsm[];
    const int tid  = threadIdx.x;
    const int wid  = tid >> 5;
    const int lane = tid & 31;
    const int wm   = wid >> 2;       // 0..1, 64 rows each
    const int wn   = wid & 3;        // 0..3, 64 cols each
    const int m0 = blockIdx.x * BM;
    const int n0 = blockIdx.y * BN;
    const uint32_t smbase = smem_u32(dynsm);

    float acc[4][8][4];
#pragma unroll
    for (int mt = 0; mt < 4; mt++)
#pragma unroll
        for (int nt = 0; nt < 8; nt++)
#pragma unroll
            for (int r = 0; r < 4; r++) acc[mt][nt][r] = 0.0f;

    const uint32_t a_row = (uint32_t)(wm * 64 + (lane & 15));
    const uint32_t a_col = (uint32_t)((lane >> 4) * 16);
    const uint32_t b_row = (uint32_t)(wn * 64 + (lane & 7) + ((lane >> 4) << 3));
    const uint32_t b_col = (uint32_t)(((lane >> 3) & 1) * 16);

    auto load_tile = [&](int s, int kt) {
        int k0 = kt * BK;
        uint32_t As = smbase + s * STAGE_BYTES;
        uint32_t Bs = As + A_STAGE;
        const char* gA = (const char*)g_A  + (size_t)k0 * 2;
        const char* gB = (const char*)g_Wc + (size_t)k0 * 2;
#pragma unroll
        for (int t = 0; t < 4; t++) {                    // A: 1024 16B ops
            int o = tid + t * 256;
            int r = o >> 3;
            int c = (o & 7) * 16;
            cp_async16(As + SW128(r * 128 + c),
                       gA + (size_t)(m0 + r) * (F2_DIM * 2) + c);
        }
#pragma unroll
        for (int t = 0; t < 8; t++) {                    // B: 2048 16B ops
            int o = tid + t * 256;
            int r = o >> 3;
            int c = (o & 7) * 16;
            cp_async16(Bs + SW128(r * 128 + c),
                       gB + (size_t)(n0 + r) * (F2_DIM * 2) + c);
        }
    };

#pragma unroll
    for (int s = 0; s < STAGES - 1; s++) {
        load_tile(s, s);
        asm volatile("cp.async.commit_group;\n");
    }

    for (int kt = 0; kt < KT; kt++) {
        asm volatile("cp.async.wait_group %0;\n" :: "n"(STAGES - 2));
        __syncthreads();

        int kn = kt + STAGES - 1;
        if (kn < KT) load_tile(kn & (STAGES - 1), kn);
        asm volatile("cp.async.commit_group;\n");

        const uint32_t As = smbase + (kt & (STAGES - 1)) * STAGE_BYTES;
        const uint32_t Bs = As + A_STAGE;
#pragma unroll
        for (int ks = 0; ks < 4; ks++) {                 // BK=64 -> 4 k16 steps
            uint32_t a[4][4], b[4][4];
#pragma unroll
            for (int mt = 0; mt < 4; mt++)
                ldsm_x4(a[mt], As + SW128((a_row + mt * 16) * 128 + ks * 32 + a_col));
#pragma unroll
            for (int n2 = 0; n2 < 4; n2++)
                ldsm_x4(b[n2], Bs + SW128((b_row + n2 * 16) * 128 + ks * 32 + b_col));
#pragma unroll
            for (int mt = 0; mt < 4; mt++)
#pragma unroll
                for (int nt = 0; nt < 8; nt++)
                    mma_f16(acc[mt][nt], a[mt], &b[nt >> 1][(nt & 1) * 2]);
        }
    }

    // epilogue: + bias, float2 stores
    const int r0 = m0 + wm * 64 + (lane >> 2);
    const int c0 = n0 + wn * 64 + (lane & 3) * 2;
#pragma unroll
    for (int mt = 0; mt < 4; mt++) {
        int row = r0 + mt * 16;
#pragma unroll
        for (int nt = 0; nt < 8; nt++) {
            int col = c0 + nt * 8;
            float2 bv = *(const float2*)(g_biasf + col);
            float2 v0 = make_float2(acc[mt][nt][0] + bv.x, acc[mt][nt][1] + bv.y);
            float2 v1 = make_float2(acc[mt][nt][2] + bv.x, acc[mt][nt][3] + bv.y);
            *(float2*)(out + (size_t)row * O_DIM + col)       = v0;
            *(float2*)(out + (size_t)(row + 8) * O_DIM + col) = v1;
        }
    }
}

// ---------------- launch ------------------------------------------------------
extern "C" void kernel_launch(void* const* d_in, const int* in_sizes, int n_in,
                              void* d_out, int out_size) {
    const float* x     = (const float*)d_in[0];
    const float* e1w   = (const float*)d_in[1];
    const float* e2w   = (const float*)d_in[2];
    const float* wvals = (const float*)d_in[3];
    const float* bvals = (const float*)d_in[4];
    const int*   e1p   = (const int*)d_in[5];
    const int*   e2p   = (const int*)d_in[6];
    const int*   wrows = (const int*)d_in[7];
    const int*   wcols = (const int*)d_in[8];
    const int*   bidx  = (const int*)d_in[9];
    float* out = (float*)d_out;

    cudaFuncSetAttribute(gemm_kernel, cudaFuncAttributeMaxDynamicSharedMemorySize,
                         DYN_SMEM);

    fused_pre_kernel<<<BA_BLOCKS + SC_BLOCKS, 256>>>(
        x, e1w, e2w, e1p, e2p, wvals, wrows, wcols, bvals, bidx);
    convw_kernel<<<(O_DIM * F2_DIM / 4 + 255) / 256, 256>>>();

    dim3 grid(B_DIM / BM, O_DIM / BN);
    gemm_kernel<<<grid, 256, DYN_SMEM>>>(out);
}

// round 12
// speedup vs baseline: 1.1350x; 1.0748x over previous
#include <cuda_runtime.h>
#include <cuda_fp16.h>
#include <stdint.h>

#define B_DIM   8192
#define F0_DIM  2048
#define F1_DIM  2304
#define F2_DIM  2560
#define O_DIM   1024
#define NNZ_DIM 262144
#define NB_DIM  1024

// ---------------- scratch (device globals; zero-initialized at load) ----------
__device__ float g_W[O_DIM * F2_DIM];
__device__ float g_bias[O_DIM];
__device__ float g_biasf[O_DIM];
__device__ __half g_A[(size_t)B_DIM * F2_DIM];    // 42 MB, fp16 h
__device__ __half g_Wc[(size_t)O_DIM * F2_DIM];   // 5.2 MB, fp16 W

// ---------------- helpers -----------------------------------------------------
__device__ __forceinline__ uint32_t smem_u32(const void* p) {
    uint32_t a;
    asm("{ .reg .u64 t; cvta.to.shared.u64 t, %1; cvt.u32.u64 %0, t; }"
        : "=r"(a) : "l"(p));
    return a;
}

#define SW128(off) ((uint32_t)(off) ^ ((((uint32_t)(off)) >> 3) & 0x70u))

__device__ __forceinline__ void cp_async16(uint32_t saddr, const void* gptr) {
    asm volatile("cp.async.cg.shared.global [%0], [%1], 16;\n"
                 :: "r"(saddr), "l"(gptr));
}

__device__ __forceinline__ void ldsm_x4(uint32_t* r, uint32_t addr) {
    asm volatile("ldmatrix.sync.aligned.m8n8.x4.shared.b16 {%0,%1,%2,%3}, [%4];"
                 : "=r"(r[0]), "=r"(r[1]), "=r"(r[2]), "=r"(r[3]) : "r"(addr));
}

__device__ __forceinline__ void mma_f16(float* d, const uint32_t* a, const uint32_t* b) {
    asm volatile(
        "mma.sync.aligned.m16n8k16.row.col.f32.f16.f16.f32 "
        "{%0,%1,%2,%3}, {%4,%5,%6,%7}, {%8,%9}, {%0,%1,%2,%3};\n"
        : "+f"(d[0]), "+f"(d[1]), "+f"(d[2]), "+f"(d[3])
        : "r"(a[0]), "r"(a[1]), "r"(a[2]), "r"(a[3]), "r"(b[0]), "r"(b[1]));
}

// ---------------- fused prologue: build A (1 row/block) + scatter -------------
#define SC_BLOCKS (NNZ_DIM / 256) /* 1024 */

__global__ void __launch_bounds__(256)
fused_pre_kernel(const float* __restrict__ x,
                 const float* __restrict__ e1w,
                 const float* __restrict__ e2w,
                 const int*   __restrict__ e1p,
                 const int*   __restrict__ e2p,
                 const float* __restrict__ w_vals,
                 const int*   __restrict__ w_rows,
                 const int*   __restrict__ w_cols,
                 const float* __restrict__ b_vals,
                 const int*   __restrict__ b_idx) {
    const int tid = threadIdx.x;

    if (blockIdx.x >= B_DIM) {
        // ---- COO weight + bias scatter (atomics into zeroed g_W / g_bias) ----
        int i = (blockIdx.x - B_DIM) * 256 + tid;
        atomicAdd(&g_W[w_rows[i] * F2_DIM + w_cols[i]], w_vals[i]);
        if (i < NB_DIM)
            atomicAdd(&g_bias[b_idx[i]], b_vals[i]);
        return;
    }

    __shared__ float sh[F2_DIM];
    const int b = blockIdx.x;

    const float4* xr = (const float4*)(x + (size_t)b * F0_DIM);
#pragma unroll
    for (int t = 0; t < F0_DIM / 4 / 256; t++)          // 2 iters
        ((float4*)sh)[tid + t * 256] = xr[tid + t * 256];
    __syncthreads();

    {   // E1 == 256 == blockDim
        int c = tid;
        float t = sh[__ldg(&e1p[c])] * __ldg(&e1w[c]);
        sh[F0_DIM + c] = fmaxf(t, 0.0f);
    }
    __syncthreads();
    {   // E2 == 256
        int c = tid;
        float t = sh[__ldg(&e2p[c])] * __ldg(&e2w[c]);
        sh[F1_DIM + c] = fmaxf(t, 0.0f);
    }
    __syncthreads();

    __half* base = g_A + (size_t)b * F2_DIM;
#pragma unroll
    for (int t = 0; t < F2_DIM / 4 / 256 + 1; t++) {    // 3 iters (last partial)
        int i = tid + t * 256;
        if (i < F2_DIM / 4) {
            float4 v = *(const float4*)(sh + i * 4);
            __half2 p0 = __floats2half2_rn(v.x, v.y);
            __half2 p1 = __floats2half2_rn(v.z, v.w);
            *(__half2*)(base + i * 4)     = p0;
            *(__half2*)(base + i * 4 + 2) = p1;
        }
    }
}

// ---------------- convw: W fp32 -> fp16, and re-zero W/bias for next replay ---
__global__ void convw_kernel() {
    int i = blockIdx.x * blockDim.x + threadIdx.x;
    if (i >= O_DIM * F2_DIM / 4) return;
    float4 v = *(const float4*)(g_W + i * 4);
    __half2 p0 = __floats2half2_rn(v.x, v.y);
    __half2 p1 = __floats2half2_rn(v.z, v.w);
    *(__half2*)(g_Wc + i * 4)     = p0;
    *(__half2*)(g_Wc + i * 4 + 2) = p1;
    *(float4*)(g_W + i * 4) = make_float4(0.f, 0.f, 0.f, 0.f);   // pre-zero for next call
    if (i < O_DIM / 4) {                                         // bias: copy then zero
        float4 b = *(const float4*)(g_bias + i * 4);
        *(float4*)(g_biasf + i * 4) = b;
        *(float4*)(g_bias + i * 4)  = make_float4(0.f, 0.f, 0.f, 0.f);
    }
}

// ---------------- fp16 HMMA GEMM: out = A @ Wc^T + bias -----------------------
// BM=64, BN=128, 128 threads (4 warps 2x2), 2 CTAs/SM, 1024 CTAs -> 1.2% imbalance
#define BM 64
#define BN 128
#define BK 64
#define NTHREADS 128
#define STAGES 4
#define A_STAGE (BM * BK * 2)               /* 8192 B */
#define B_STAGE (BN * BK * 2)               /* 16384 B */
#define STAGE_BYTES (A_STAGE + B_STAGE)     /* 24576 B */
#define KT (F2_DIM / BK)                    /* 40 */
#define DYN_SMEM (STAGES * STAGE_BYTES)     /* 98304 B -> 2 CTAs/SM */

__global__ void __launch_bounds__(NTHREADS, 2)
gemm_kernel(float* __restrict__ out) {
    extern __shared__ char dynsm[];
    const int tid  = threadIdx.x;
    const int wid  = tid >> 5;
    const int lane = tid & 31;
    const int wm   = wid >> 1;       // 0..1, 32 rows each
    const int wn   = wid & 1;        // 0..1, 64 cols each
    const int n0 = blockIdx.x * BN;  // n fast -> CTAs sharing A rows co-run
    const int m0 = blockIdx.y * BM;
    const uint32_t smbase = smem_u32(dynsm);

    float acc[2][8][4];
#pragma unroll
    for (int mt = 0; mt < 2; mt++)
#pragma unroll
        for (int nt = 0; nt < 8; nt++)
#pragma unroll
            for (int r = 0; r < 4; r++) acc[mt][nt][r] = 0.0f;

    // ldmatrix lane address components (logical, pre-swizzle, byte units)
    const uint32_t a_row = (uint32_t)(wm * 32 + (lane & 15));
    const uint32_t a_col = (uint32_t)((lane >> 4) * 16);
    const uint32_t b_row = (uint32_t)(wn * 64 + (lane & 7) + ((lane >> 4) << 3));
    const uint32_t b_col = (uint32_t)(((lane >> 3) & 1) * 16);

    auto load_tile = [&](int s, int kt) {
        int k0 = kt * BK;
        uint32_t As = smbase + s * STAGE_BYTES;
        uint32_t Bs = As + A_STAGE;
        const char* gA = (const char*)g_A  + (size_t)k0 * 2;
        const char* gB = (const char*)g_Wc + (size_t)k0 * 2;
#pragma unroll
        for (int t = 0; t < 4; t++) {                    // A: 512 16B ops
            int o = tid + t * NTHREADS;
            int r = o >> 3;
            int c = (o & 7) * 16;
            cp_async16(As + SW128(r * 128 + c),
                       gA + (size_t)(m0 + r) * (F2_DIM * 2) + c);
        }
#pragma unroll
        for (int t = 0; t < 8; t++) {                    // B: 1024 16B ops
            int o = tid + t * NTHREADS;
            int r = o >> 3;
            int c = (o & 7) * 16;
            cp_async16(Bs + SW128(r * 128 + c),
                       gB + (size_t)(n0 + r) * (F2_DIM * 2) + c);
        }
    };

#pragma unroll
    for (int s = 0; s < STAGES - 1; s++) {
        load_tile(s, s);
        asm volatile("cp.async.commit_group;\n");
    }

    for (int kt = 0; kt < KT; kt++) {
        asm volatile("cp.async.wait_group %0;\n" :: "n"(STAGES - 2));
        __syncthreads();

        int kn = kt + STAGES - 1;
        if (kn < KT) load_tile(kn & (STAGES - 1), kn);
        asm volatile("cp.async.commit_group;\n");

        const uint32_t As = smbase + (kt & (STAGES - 1)) * STAGE_BYTES;
        const uint32_t Bs = As + A_STAGE;
#pragma unroll
        for (int ks = 0; ks < 4; ks++) {                 // BK=64 -> 4 k16 steps
            uint32_t a[2][4], b[4][4];
#pragma unroll
            for (int mt = 0; mt < 2; mt++)
                ldsm_x4(a[mt], As + SW128((a_row + mt * 16) * 128 + ks * 32 + a_col));
#pragma unroll
            for (int n2 = 0; n2 < 4; n2++)
                ldsm_x4(b[n2], Bs + SW128((b_row + n2 * 16) * 128 + ks * 32 + b_col));
#pragma unroll
            for (int mt = 0; mt < 2; mt++)
#pragma unroll
                for (int nt = 0; nt < 8; nt++)
                    mma_f16(acc[mt][nt], a[mt], &b[nt >> 1][(nt & 1) * 2]);
        }
    }

    // epilogue: + bias, float2 stores
    const int r0 = m0 + wm * 32 + (lane >> 2);
    const int c0 = n0 + wn * 64 + (lane & 3) * 2;
#pragma unroll
    for (int mt = 0; mt < 2; mt++) {
        int row = r0 + mt * 16;
#pragma unroll
        for (int nt = 0; nt < 8; nt++) {
            int col = c0 + nt * 8;
            float2 bv = *(const float2*)(g_biasf + col);
            float2 v0 = make_float2(acc[mt][nt][0] + bv.x, acc[mt][nt][1] + bv.y);
            float2 v1 = make_float2(acc[mt][nt][2] + bv.x, acc[mt][nt][3] + bv.y);
            *(float2*)(out + (size_t)row * O_DIM + col)       = v0;
            *(float2*)(out + (size_t)(row + 8) * O_DIM + col) = v1;
        }
    }
}

// ---------------- launch ------------------------------------------------------
extern "C" void kernel_launch(void* const* d_in, const int* in_sizes, int n_in,
                              void* d_out, int out_size) {
    const float* x     = (const float*)d_in[0];
    const float* e1w   = (const float*)d_in[1];
    const float* e2w   = (const float*)d_in[2];
    const float* wvals = (const float*)d_in[3];
    const float* bvals = (const float*)d_in[4];
    const int*   e1p   = (const int*)d_in[5];
    const int*   e2p   = (const int*)d_in[6];
    const int*   wrows = (const int*)d_in[7];
    const int*   wcols = (const int*)d_in[8];
    const int*   bidx  = (const int*)d_in[9];
    float* out = (float*)d_out;

    cudaFuncSetAttribute(gemm_kernel, cudaFuncAttributeMaxDynamicSharedMemorySize,
                         DYN_SMEM);

    fused_pre_kernel<<<B_DIM + SC_BLOCKS, 256>>>(
        x, e1w, e2w, e1p, e2p, wvals, wrows, wcols, bvals, bidx);
    convw_kernel<<<(O_DIM * F2_DIM / 4 + 255) / 256, 256>>>();

    dim3 grid(O_DIM / BN, B_DIM / BM);     // n fast, m slow
    gemm_kernel<<<grid, NTHREADS, DYN_SMEM>>>(out);
}